// round 14
// baseline (speedup 1.0000x reference)
#include <cuda_runtime.h>
#include <cooperative_groups.h>
#include <math.h>

namespace cg = cooperative_groups;

#define Mdim 512
#define Ndim 2048
#define Bsz  4
#define Lnum 20
#define CAP  24576            // global nnz cap (E[nnz]=20971)
#define ROWCAP 96
#define MNdim (Mdim*Ndim)
#define EPSV 1e-6f
#define NTH  1024
#define CLSZ 16
#define RPC (Mdim/CLSZ)       // 32 rows per CTA
#define CPC (Ndim/CLSZ)       // 128 cols per CTA
#define LCAP 1792             // per-CTA entry cap (E=1311, sd~36, +13.4 sigma), mult of 4
#define SLOTS (CLSZ*LCAP)     // 28672

#define CLUSTER_ARRIVE() asm volatile("barrier.cluster.arrive.aligned;" ::: "memory")
#define CLUSTER_WAIT()   asm volatile("barrier.cluster.wait.aligned;" ::: "memory")

// ---------------- device scratch ----------------
__device__ int            g_deg[Mdim];
__device__ int            g_rowptr[Mdim + 1];
__device__ int            g_nnz;
__device__ unsigned short g_stage[Mdim * ROWCAP];
__device__ unsigned       g_lin[CAP];          // CSR linear indices
__device__ unsigned short g_permS[SLOTS];      // slice-local CSC pos -> local CSR pos
__device__ unsigned       g_linS[SLOTS];       // slice-local CSC linear indices
__device__ int            g_scnt[CLSZ];
__device__ int            g_colptr[CLSZ * (Ndim + 1)];
__device__ __align__(16) float2 g_wmn[(size_t)Lnum * SLOTS]; // {mwde[l], wde[l+1]} CSC slice-local
__device__ float          g_rho[Lnum];

__device__ __forceinline__ void cpasync16(unsigned dst, const void* src) {
    asm volatile("cp.async.ca.shared.global [%0], [%1], 16;" :: "r"(dst), "l"(src));
}

// ---------------- P1: block per row — degree + staged column list ----------------
__global__ void k_prep1(const float4* __restrict__ H4) {
    __shared__ int s_cnt;
    __shared__ unsigned short s_cols[ROWCAP];
    const int i = blockIdx.x;
    const int t = threadIdx.x;       // 512 threads, one float4 each
    const int lane = t & 31;
    if (t == 0) s_cnt = 0;
    __syncthreads();
    float4 v = H4[(size_t)i * (Ndim / 4) + t];
    int cnt = (v.x != 0.0f) + (v.y != 0.0f) + (v.z != 0.0f) + (v.w != 0.0f);
    int sc = cnt;
    for (int o = 1; o < 32; o <<= 1) {
        int u = __shfl_up_sync(0xffffffffu, sc, o);
        if (lane >= o) sc += u;
    }
    int total = __shfl_sync(0xffffffffu, sc, 31);
    int base = 0;
    if (lane == 31 && total) base = atomicAdd(&s_cnt, total);
    base = __shfl_sync(0xffffffffu, base, 31);
    int idx = base + sc - cnt;
    int c = t * 4;
    if (v.x != 0.0f && idx < ROWCAP) s_cols[idx++] = (unsigned short)c;
    if (v.y != 0.0f && idx < ROWCAP) s_cols[idx++] = (unsigned short)(c + 1);
    if (v.z != 0.0f && idx < ROWCAP) s_cols[idx++] = (unsigned short)(c + 2);
    if (v.w != 0.0f && idx < ROWCAP) s_cols[idx++] = (unsigned short)(c + 3);
    __syncthreads();
    int d = min(s_cnt, ROWCAP);
    if (t == 0) g_deg[i] = d;
    if (t < d) g_stage[i * ROWCAP + t] = s_cols[t];
}

// ---------------- P2: scan + expand CSR + softmax + zero out ----------------
__global__ void k_prep2(const float* __restrict__ rhos, float* __restrict__ out) {
    __shared__ int s[Mdim];
    const int t = threadIdx.x;
    s[t] = g_deg[t];
    __syncthreads();
    for (int off = 1; off < Mdim; off <<= 1) {
        int v = (t >= off) ? s[t - off] : 0;
        __syncthreads();
        s[t] += v;
        __syncthreads();
    }
    g_rowptr[t + 1] = s[t];
    if (t == 0) g_rowptr[0] = 0;
    if (t == Mdim - 1) g_nnz = s[Mdim - 1];
    int st = s[t] - g_deg[t];
    int d  = g_deg[t];
    unsigned lbase = (unsigned)(t * Ndim);
    for (int k = 0; k < d; k++) {
        int idx = st + k;
        if (idx < CAP) g_lin[idx] = lbase + g_stage[t * ROWCAP + k];
    }
    if (t == 0) {
        *out = 0.0f;
        float mx = -1e30f;
        for (int l = 0; l < Lnum; l++) mx = fmaxf(mx, rhos[l]);
        float e[Lnum], sm = 0.0f;
        for (int l = 0; l < Lnum; l++) { e[l] = expf(rhos[l] - mx); sm += e[l]; }
        float inv = 1.0f / sm;
        for (int l = 0; l < Lnum; l++) g_rho[l] = e[l] * inv;
    }
}

// ---------------- P3: per-slice CSC (slice-local layout), grid=CLSZ ----------------
__global__ void k_prep3() {
    __shared__ int s_hist[Ndim];
    __shared__ int s_cp[Ndim + 1];
    __shared__ int s_wsum[32];
    const int blk = blockIdx.x;
    const int t = threadIdx.x;
    const int lane = t & 31;
    const int wid = t >> 5;
    const int r0 = blk * RPC;
    const int kbase = g_rowptr[r0];
    int kend = g_rowptr[r0 + RPC];
    if (kend - kbase > LCAP) kend = kbase + LCAP;
    const int cnt = kend - kbase;

    s_hist[t] = 0; s_hist[t + 1024] = 0;
    __syncthreads();
    for (int k = t; k < cnt; k += 1024)
        atomicAdd(&s_hist[g_lin[kbase + k] & (Ndim - 1)], 1);
    __syncthreads();
    int a = s_hist[2 * t], b = s_hist[2 * t + 1];
    int ssum = a + b;
    int sc = ssum;
    for (int o = 1; o < 32; o <<= 1) {
        int u = __shfl_up_sync(0xffffffffu, sc, o);
        if (lane >= o) sc += u;
    }
    if (lane == 31) s_wsum[wid] = sc;
    __syncthreads();
    if (wid == 0) {
        int v = s_wsum[lane];
        for (int o = 1; o < 32; o <<= 1) {
            int u = __shfl_up_sync(0xffffffffu, v, o);
            if (lane >= o) v += u;
        }
        s_wsum[lane] = v;
    }
    __syncthreads();
    int incl = sc + ((wid > 0) ? s_wsum[wid - 1] : 0);
    int excl = incl - ssum;
    s_cp[2 * t] = excl;
    s_cp[2 * t + 1] = excl + a;
    if (t == 1023) s_cp[Ndim] = incl;
    __syncthreads();
    s_hist[2 * t] = s_cp[2 * t];
    s_hist[2 * t + 1] = s_cp[2 * t + 1];
    g_colptr[blk * (Ndim + 1) + 2 * t]     = s_cp[2 * t];
    g_colptr[blk * (Ndim + 1) + 2 * t + 1] = s_cp[2 * t + 1];
    if (t == 1023) g_colptr[blk * (Ndim + 1) + Ndim] = s_cp[Ndim];
    if (t == 0) g_scnt[blk] = cnt;
    __syncthreads();
    for (int k = t; k < cnt; k += 1024) {
        unsigned lin = g_lin[kbase + k];
        int j = lin & (Ndim - 1);
        int pos = atomicAdd(&s_hist[j], 1);
        g_permS[blk * LCAP + pos] = (unsigned short)k;
        g_linS[blk * LCAP + pos]  = lin;
    }
}

// ---------------- P4: gather — one thread per (entry, 5-layer group) ----------------
#define GQ 5                                 // layers per thread
#define GGROUPS (Lnum / GQ)                  // 4
__global__ void k_gather(const float* __restrict__ wde, const float* __restrict__ mwde) {
    const int nb = (SLOTS + 255) / 256;
    const int grp = blockIdx.x / nb;            // 0..3
    const int e = (blockIdx.x - grp * nb) * 256 + threadIdx.x;
    if (e >= SLOTS) return;
    const int blk = e / LCAP;
    const int k = e - blk * LCAP;
    const bool valid = (k < g_scnt[blk]);
    const unsigned lin = valid ? g_linS[e] : 0u;
    const int l0 = grp * GQ;
    float wm[GQ], wn[GQ];
    #pragma unroll
    for (int i = 0; i < GQ; i++) wm[i] = __ldg(&mwde[(size_t)(l0 + i) * MNdim + lin]);
    #pragma unroll
    for (int i = 0; i < GQ; i++) {
        int ln = l0 + i + 1;
        wn[i] = (ln < Lnum) ? __ldg(&wde[(size_t)ln * MNdim + lin]) : 0.0f;
    }
    #pragma unroll
    for (int i = 0; i < GQ; i++) {
        float2 p; p.x = wm[i]; p.y = wn[i];
        g_wmn[(size_t)(l0 + i) * SLOTS + e] = p;
    }
}

// ---------------- main BP recurrence: CLSZ=16, double-buffered weight staging ----------------
// floats: msgs LCAP | wmn 2*2*LCAP | colC N | colP N | belP N | sign2 R | offf R |
//         err C | misc 96 ; int rpt R+4 ; u16: lin LCAP | perm LCAP | cptr N+4
#define SMEM_BYTES ((5*LCAP + 3*Ndim + 2*RPC + CPC + 96 + (RPC + 4)) * 4 \
                    + (2*LCAP + Ndim + 4) * 2)

__global__ void __launch_bounds__(NTH, 1) __cluster_dims__(CLSZ, 1, 1)
k_main(const int*   __restrict__ synd,
       const int*   __restrict__ errs,
       const float* __restrict__ llrs,
       const float* __restrict__ wllr,
       const float* __restrict__ mwllr,
       const float* __restrict__ resw,
       float* __restrict__ out)
{
    extern __shared__ char sm_raw[];
    float*  s_msgs  = (float*)sm_raw;                // LCAP
    float2* s_wmn   = (float2*)(s_msgs + LCAP);      // 2 x LCAP float2 (parity buffers)
    float*  s_colC  = (float*)(s_wmn + 2 * LCAP);    // N (combined, read in phase B)
    float*  s_colP  = s_colC + Ndim;                 // N (partials, direct store)
    float*  s_belP  = s_colP + Ndim;                 // N
    float*  s_sign2 = s_belP + Ndim;                 // R
    float*  s_offf  = s_sign2 + RPC;                 // R
    float*  s_err   = s_offf + RPC;                  // C
    float*  s_resw  = s_err + CPC;                   // 32
    float*  s_rho   = s_resw + 32;                   // 32
    float*  s_lacc  = s_rho + 32;                    // 32
    int*    s_rpt   = (int*)(s_lacc + 32);           // R+1 (+pad)
    unsigned short* s_lin  = (unsigned short*)(s_rpt + RPC + 4);  // LCAP
    unsigned short* s_perm = s_lin + LCAP;                         // LCAP
    unsigned short* s_cptr = s_perm + LCAP;                        // N+1 (+pad)

    cg::cluster_group cl = cg::this_cluster();
    const int rank = (int)cl.block_rank();
    const int b    = blockIdx.x / CLSZ;
    const int tid  = threadIdx.x;
    const int lane = tid & 31;
    const int wid  = tid >> 5;
    const float OME = 1.0f - EPSV;
    const unsigned u_wmn = (unsigned)__cvta_generic_to_shared(s_wmn);

    const int r0 = rank * RPC;
    const int kbase = g_rowptr[r0];
    int kend = g_rowptr[r0 + RPC];
    if (kend - kbase > LCAP) kend = kbase + LCAP;
    const int cnt = kend - kbase;
    const int n16 = (cnt + 1) >> 1;     // 16B chunks (2 float2 per chunk)

    // ---- prologue ----
    for (int k = tid; k < cnt; k += NTH) {
        s_lin[k]  = (unsigned short)(g_lin[kbase + k] & (Ndim - 1));
        s_perm[k] = g_permS[rank * LCAP + k];
        s_msgs[k] = 0.0f;
    }
    for (int j = tid; j <= Ndim; j += NTH)
        s_cptr[j] = (unsigned short)g_colptr[rank * (Ndim + 1) + j];
    if (tid <= RPC) s_rpt[tid] = g_rowptr[r0 + tid] - kbase;
    if (tid < RPC) {
        int row = r0 + tid;
        s_sign2[tid] = 2.0f * (1.0f - 2.0f * (float)synd[b * Mdim + row]);
        int d = g_rowptr[row + 1] - g_rowptr[row];
        s_offf[tid] = powf(OME, (float)(Ndim - d));
    }
    if (tid < CPC)
        s_err[tid] = 1.0f - (float)errs[b * Ndim + rank * CPC + tid];
    if (tid < Lnum) { s_resw[tid] = resw[tid]; s_rho[tid] = g_rho[tid]; }
    for (int j = tid; j < Ndim; j += NTH)
        s_colC[j] = llrs[j] * wllr[j];     // layer-0 combined column input
    // stage layer-0 weights into parity-0 buffer
    {
        const float2* src = &g_wmn[rank * LCAP];
        for (int q = tid; q < n16; q += NTH)
            cpasync16(u_wmn + (unsigned)q * 16u, src + q * 2);
        asm volatile("cp.async.commit_group;");
    }
    __syncthreads();

    float acc = 0.0f;
    for (int l = 0; l < Lnum; l++) {
        const float rw = s_resw[l];
        const bool lastL = (l == Lnum - 1);
        const int par = l & 1;

        // ---- prefetch NEXT layer's weights into other parity (lands during this layer) ----
        if (!lastL) {
            const float2* src = &g_wmn[(size_t)(l + 1) * SLOTS + rank * LCAP];
            const unsigned dst = u_wmn + (unsigned)((par ^ 1) * LCAP) * 8u;
            for (int q = tid; q < n16; q += NTH)
                cpasync16(dst + (unsigned)q * 16u, src + q * 2);
        }
        asm volatile("cp.async.commit_group;");

        // ---- phase B: fused warp-per-row (1 row/warp) ----
        if (wid < RPC) {
            const int rr = wid;
            const int st = s_rpt[rr], en = s_rpt[rr + 1];
            const int k0 = st + lane, k1 = k0 + 32, k2 = k1 + 32;
            float d0 = 1.0f, d1 = 1.0f, d2 = 1.0f;
            float prod = 1.0f;
            if (k0 < en) {
                float men = s_colC[s_lin[k0]] - s_msgs[k0];
                asm("tanh.approx.f32 %0, %1;" : "=f"(d0) : "f"(0.5f * men));
                if (d0 == 0.0f) d0 = 1.0f;
                d0 = fminf(fmaxf(d0, -OME), OME);
                prod *= d0;
            }
            if (k1 < en) {
                float men = s_colC[s_lin[k1]] - s_msgs[k1];
                asm("tanh.approx.f32 %0, %1;" : "=f"(d1) : "f"(0.5f * men));
                if (d1 == 0.0f) d1 = 1.0f;
                d1 = fminf(fmaxf(d1, -OME), OME);
                prod *= d1;
            }
            if (k2 < en) {
                float men = s_colC[s_lin[k2]] - s_msgs[k2];
                asm("tanh.approx.f32 %0, %1;" : "=f"(d2) : "f"(0.5f * men));
                if (d2 == 0.0f) d2 = 1.0f;
                d2 = fminf(fmaxf(d2, -OME), OME);
                prod *= d2;
            }
            #pragma unroll
            for (int o = 16; o; o >>= 1) prod *= __shfl_xor_sync(0xffffffffu, prod, o);
            const float P = prod * s_offf[rr];
            const float sg = s_sign2[rr];
            if (k0 < en) {
                float r = __fdividef(P, d0);
                float ath = (fabsf(r) < 6.25e-3f) ? r * (1.0f + (1.0f / 3.0f) * r * r)
                                                  : atanhf(r);
                s_msgs[k0] = sg * ath + rw * s_msgs[k0];
            }
            if (k1 < en) {
                float r = __fdividef(P, d1);
                float ath = (fabsf(r) < 6.25e-3f) ? r * (1.0f + (1.0f / 3.0f) * r * r)
                                                  : atanhf(r);
                s_msgs[k1] = sg * ath + rw * s_msgs[k1];
            }
            if (k2 < en) {
                float r = __fdividef(P, d2);
                float ath = (fabsf(r) < 6.25e-3f) ? r * (1.0f + (1.0f / 3.0f) * r * r)
                                                  : atanhf(r);
                s_msgs[k2] = sg * ath + rw * s_msgs[k2];
            }
        }
        // retire THIS layer's staging group (prefetch for l+1 stays in flight)
        if (!lastL) asm volatile("cp.async.wait_group 1;" ::: "memory");
        else        asm volatile("cp.async.wait_group 0;" ::: "memory");
        __syncthreads();   // msgs + this layer's weights visible to all

        // ---- phase C: column-parallel CSC partial sums (2 cols/thread) ----
        {
            const float2* wbuf = s_wmn + par * LCAP;
            const int j0 = tid * 2;
            #pragma unroll
            for (int jj = 0; jj < 2; jj++) {
                const int j = j0 + jj;
                const int st = s_cptr[j], en = s_cptr[j + 1];
                float cs = 0.0f, bs = 0.0f;
                for (int t = st; t < en; t++) {
                    float m = s_msgs[s_perm[t]];
                    float2 w = wbuf[t];
                    bs += m * w.x;
                    cs += m * w.y;
                }
                s_belP[j] = bs;
                s_colP[j] = cs;
            }
        }
        CLUSTER_ARRIVE();
        CLUSTER_WAIT();

        // ---- cluster combine (slice-owned, float4 DSMEM, 16 peers) + loss ----
        if (tid < CPC / 4) {                 // 32 threads: column combine + broadcast
            if (!lastL) {
                int f4 = rank * (CPC / 4) + tid;
                float4 lv = ((const float4*)llrs)[f4];
                float4 wv = ((const float4*)(wllr + (size_t)(l + 1) * Ndim))[f4];
                float4 s;
                s.x = lv.x * wv.x; s.y = lv.y * wv.y;
                s.z = lv.z * wv.z; s.w = lv.w * wv.w;
                #pragma unroll
                for (int r = 0; r < CLSZ; r++) {
                    float4 p = ((const float4*)cl.map_shared_rank(s_colP, r))[f4];
                    s.x += p.x; s.y += p.y; s.z += p.z; s.w += p.w;
                }
                #pragma unroll
                for (int r = 0; r < CLSZ; r++)
                    ((float4*)cl.map_shared_rank(s_colC, r))[f4] = s;
            }
        } else if (tid < 2 * (CPC / 4)) {    // 32 threads: belief combine + loss
            int f4l = tid - CPC / 4;
            int f4 = rank * (CPC / 4) + f4l;
            float4 lv = ((const float4*)llrs)[f4];
            float4 wv = ((const float4*)(mwllr + (size_t)l * Ndim))[f4];
            float4 x;
            x.x = lv.x * wv.x; x.y = lv.y * wv.y;
            x.z = lv.z * wv.z; x.w = lv.w * wv.w;
            #pragma unroll
            for (int r = 0; r < CLSZ; r++) {
                float4 p = ((const float4*)cl.map_shared_rank(s_belP, r))[f4];
                x.x += p.x; x.y += p.y; x.z += p.z; x.w += p.w;
            }
            int jj = f4l * 4;
            float ls = 0.0f;
            ls += fmaxf(x.x, 0.0f) + log1pf(__expf(-fabsf(x.x))) - s_err[jj]     * x.x;
            ls += fmaxf(x.y, 0.0f) + log1pf(__expf(-fabsf(x.y))) - s_err[jj + 1] * x.y;
            ls += fmaxf(x.z, 0.0f) + log1pf(__expf(-fabsf(x.z))) - s_err[jj + 2] * x.z;
            ls += fmaxf(x.w, 0.0f) + log1pf(__expf(-fabsf(x.w))) - s_err[jj + 3] * x.w;
            acc += s_rho[l] * ls;
        }
        CLUSTER_ARRIVE();
        CLUSTER_WAIT();
    }

    // ---- loss reduce: acc lives in warp 1 (threads 32..63) ----
    for (int o = 16; o; o >>= 1) acc += __shfl_xor_sync(0xffffffffu, acc, o);
    if (wid == 1 && lane == 0) s_lacc[0] = acc;
    __syncthreads();
    if (tid == 0) atomicAdd(out, s_lacc[0] * (1.0f / (float)Bsz));
}

// ---------------- host launcher ----------------
extern "C" void kernel_launch(void* const* d_in, const int* in_sizes, int n_in,
                              void* d_out, int out_size) {
    const int*   synd  = (const int*)d_in[0];
    const int*   errs  = (const int*)d_in[1];
    const float* H     = (const float*)d_in[2];
    const float* llrs  = (const float*)d_in[3];
    const float* wde   = (const float*)d_in[4];
    const float* wllr  = (const float*)d_in[5];
    const float* mwde  = (const float*)d_in[6];
    const float* mwllr = (const float*)d_in[7];
    const float* rhos  = (const float*)d_in[8];
    const float* resw  = (const float*)d_in[9];
    float* out = (float*)d_out;

    cudaFuncSetAttribute(k_main, cudaFuncAttributeMaxDynamicSharedMemorySize, SMEM_BYTES);
    cudaFuncSetAttribute(k_main, cudaFuncAttributeNonPortableClusterSizeAllowed, 1);

    k_prep1<<<Mdim, 512>>>((const float4*)H);
    k_prep2<<<1, Mdim>>>(rhos, out);
    k_prep3<<<CLSZ, 1024>>>();
    k_gather<<<GGROUPS * ((SLOTS + 255) / 256), 256>>>(wde, mwde);
    k_main<<<Bsz * CLSZ, NTH, SMEM_BYTES>>>(synd, errs, llrs, wllr, mwllr, resw, out);
}

// round 15
// speedup vs baseline: 1.0906x; 1.0906x over previous
#include <cuda_runtime.h>
#include <cooperative_groups.h>
#include <math.h>

namespace cg = cooperative_groups;

#define Mdim 512
#define Ndim 2048
#define Bsz  4
#define Lnum 20
#define CAP  24576            // global nnz cap (E[nnz]=20971)
#define ROWCAP 96
#define MNdim (Mdim*Ndim)
#define EPSV 1e-6f
#define NTH  1024
#define CLSZ 16
#define CPC (Ndim/CLSZ)       // 128 cols owned per CTA
#define ROWN (Mdim/CLSZ)      // 32 rows owned per CTA (combine only)
#define LCAP 1792             // per-CTA entry cap (E=1311, sd~36), mult of 4
#define SLOTS (CLSZ*LCAP)     // 28672

#define CLUSTER_ARRIVE() asm volatile("barrier.cluster.arrive.aligned;" ::: "memory")
#define CLUSTER_WAIT()   asm volatile("barrier.cluster.wait.aligned;" ::: "memory")

// ---------------- device scratch ----------------
__device__ int            g_deg[Mdim];
__device__ int            g_rowptr[Mdim + 1];
__device__ int            g_nnz;
__device__ unsigned short g_stage[Mdim * ROWCAP];
__device__ unsigned       g_lin[CAP];              // CSR linear indices
__device__ unsigned       g_linS[SLOTS];           // per-col-slice CSC linear indices
__device__ unsigned short g_rowE[SLOTS];           // CSC pos -> global row (0..511)
__device__ unsigned char  g_jE[SLOTS];             // CSC pos -> local col (0..127)
__device__ unsigned short g_permR[SLOTS];          // row-grouped pos -> CSC pos
__device__ int            g_scnt[CLSZ];
__device__ int            g_colptrS[CLSZ * (CPC + 1)];
__device__ int            g_rowptrR[CLSZ * (Mdim + 1)];
__device__ __align__(16) float2 g_wmn[(size_t)Lnum * SLOTS]; // {mwde[l], wde[l+1]} slice-CSC
__device__ float          g_rho[Lnum];

__device__ __forceinline__ void cpasync16(unsigned dst, const void* src) {
    asm volatile("cp.async.ca.shared.global [%0], [%1], 16;" :: "r"(dst), "l"(src));
}

// ---------------- P1: block per row — degree + staged column list ----------------
__global__ void k_prep1(const float4* __restrict__ H4) {
    __shared__ int s_cnt;
    __shared__ unsigned short s_cols[ROWCAP];
    const int i = blockIdx.x;
    const int t = threadIdx.x;       // 512 threads, one float4 each
    const int lane = t & 31;
    if (t == 0) s_cnt = 0;
    __syncthreads();
    float4 v = H4[(size_t)i * (Ndim / 4) + t];
    int cnt = (v.x != 0.0f) + (v.y != 0.0f) + (v.z != 0.0f) + (v.w != 0.0f);
    int sc = cnt;
    for (int o = 1; o < 32; o <<= 1) {
        int u = __shfl_up_sync(0xffffffffu, sc, o);
        if (lane >= o) sc += u;
    }
    int total = __shfl_sync(0xffffffffu, sc, 31);
    int base = 0;
    if (lane == 31 && total) base = atomicAdd(&s_cnt, total);
    base = __shfl_sync(0xffffffffu, base, 31);
    int idx = base + sc - cnt;
    int c = t * 4;
    if (v.x != 0.0f && idx < ROWCAP) s_cols[idx++] = (unsigned short)c;
    if (v.y != 0.0f && idx < ROWCAP) s_cols[idx++] = (unsigned short)(c + 1);
    if (v.z != 0.0f && idx < ROWCAP) s_cols[idx++] = (unsigned short)(c + 2);
    if (v.w != 0.0f && idx < ROWCAP) s_cols[idx++] = (unsigned short)(c + 3);
    __syncthreads();
    int d = min(s_cnt, ROWCAP);
    if (t == 0) g_deg[i] = d;
    if (t < d) g_stage[i * ROWCAP + t] = s_cols[t];
}

// ---------------- P2: scan + expand CSR + softmax + zero out ----------------
__global__ void k_prep2(const float* __restrict__ rhos, float* __restrict__ out) {
    __shared__ int s[Mdim];
    const int t = threadIdx.x;
    s[t] = g_deg[t];
    __syncthreads();
    for (int off = 1; off < Mdim; off <<= 1) {
        int v = (t >= off) ? s[t - off] : 0;
        __syncthreads();
        s[t] += v;
        __syncthreads();
    }
    g_rowptr[t + 1] = s[t];
    if (t == 0) g_rowptr[0] = 0;
    if (t == Mdim - 1) g_nnz = s[Mdim - 1];
    int st = s[t] - g_deg[t];
    int d  = g_deg[t];
    unsigned lbase = (unsigned)(t * Ndim);
    for (int k = 0; k < d; k++) {
        int idx = st + k;
        if (idx < CAP) g_lin[idx] = lbase + g_stage[t * ROWCAP + k];
    }
    if (t == 0) {
        *out = 0.0f;
        float mx = -1e30f;
        for (int l = 0; l < Lnum; l++) mx = fmaxf(mx, rhos[l]);
        float e[Lnum], sm = 0.0f;
        for (int l = 0; l < Lnum; l++) { e[l] = expf(rhos[l] - mx); sm += e[l]; }
        float inv = 1.0f / sm;
        for (int l = 0; l < Lnum; l++) g_rho[l] = e[l] * inv;
    }
}

// ---------------- P3: per COLUMN-slice CSC + row-grouped perm; grid=CLSZ ----------------
__global__ void k_prep3() {
    __shared__ int s_hist[Mdim];
    __shared__ int s_cur[Mdim];
    __shared__ int s_cp[CPC + 1];
    __shared__ int s_wsum[32];
    const int blk = blockIdx.x;
    const int t = threadIdx.x;
    const int lane = t & 31;
    const int wid = t >> 5;
    const int j0 = blk * CPC;
    const int nnz = min(g_nnz, CAP);

    // --- column histogram over owned 128 columns ---
    if (t < CPC) s_hist[t] = 0;
    __syncthreads();
    for (int k = t; k < nnz; k += 1024) {
        int jl = (int)(g_lin[k] & (Ndim - 1)) - j0;
        if ((unsigned)jl < (unsigned)CPC) atomicAdd(&s_hist[jl], 1);
    }
    __syncthreads();
    // scan 128 (warps 0-3)
    if (t < CPC) {
        int v = s_hist[t], sc = v;
        for (int o = 1; o < 32; o <<= 1) {
            int u = __shfl_up_sync(0xffffffffu, sc, o);
            if (lane >= o) sc += u;
        }
        if (lane == 31) s_wsum[wid] = sc;
    }
    __syncthreads();
    if (t == 0) { int r = 0; for (int w = 0; w < CPC / 32; w++) { int x = s_wsum[w]; s_wsum[w] = r; r += x; } }
    __syncthreads();
    if (t < CPC) {
        int v = s_hist[t], sc = v;
        for (int o = 1; o < 32; o <<= 1) {
            int u = __shfl_up_sync(0xffffffffu, sc, o);
            if (lane >= o) sc += u;
        }
        int excl = sc - v + s_wsum[wid];
        s_cp[t] = excl; s_cur[t] = excl;
        if (t == CPC - 1) s_cp[CPC] = excl + v;
    }
    __syncthreads();
    const int cnt = min(s_cp[CPC], LCAP);
    if (t == 0) g_scnt[blk] = cnt;
    if (t <= CPC) g_colptrS[blk * (CPC + 1) + t] = min(s_cp[t], LCAP);
    // scatter CSC (intra-column order arbitrary)
    for (int k = t; k < nnz; k += 1024) {
        unsigned lin = g_lin[k];
        int jl = (int)(lin & (Ndim - 1)) - j0;
        if ((unsigned)jl < (unsigned)CPC) {
            int pos = atomicAdd(&s_cur[jl], 1);
            if (pos < LCAP) {
                g_linS[blk * LCAP + pos] = lin;
                g_rowE[blk * LCAP + pos] = (unsigned short)(lin >> 11);
                g_jE[blk * LCAP + pos]   = (unsigned char)jl;
            }
        }
    }
    __syncthreads();

    // --- row histogram (512 rows) over stored entries ---
    if (t < Mdim) s_hist[t] = 0;
    __syncthreads();
    for (int k = t; k < cnt; k += 1024)
        atomicAdd(&s_hist[g_rowE[blk * LCAP + k]], 1);
    __syncthreads();
    // scan 512 (warps 0-15)
    if (t < Mdim) {
        int v = s_hist[t], sc = v;
        for (int o = 1; o < 32; o <<= 1) {
            int u = __shfl_up_sync(0xffffffffu, sc, o);
            if (lane >= o) sc += u;
        }
        if (lane == 31) s_wsum[wid] = sc;
    }
    __syncthreads();
    if (t == 0) { int r = 0; for (int w = 0; w < Mdim / 32; w++) { int x = s_wsum[w]; s_wsum[w] = r; r += x; } }
    __syncthreads();
    if (t < Mdim) {
        int v = s_hist[t], sc = v;
        for (int o = 1; o < 32; o <<= 1) {
            int u = __shfl_up_sync(0xffffffffu, sc, o);
            if (lane >= o) sc += u;
        }
        int excl = sc - v + s_wsum[wid];
        s_cur[t] = excl;
        g_rowptrR[blk * (Mdim + 1) + t] = excl;
        if (t == Mdim - 1) g_rowptrR[blk * (Mdim + 1) + Mdim] = excl + v;
    }
    __syncthreads();
    for (int k = t; k < cnt; k += 1024) {
        int row = g_rowE[blk * LCAP + k];
        int pos = atomicAdd(&s_cur[row], 1);
        g_permR[blk * LCAP + pos] = (unsigned short)k;
    }
}

// ---------------- P4: gather — one thread per (entry, 5-layer group) ----------------
#define GQ 5
#define GGROUPS (Lnum / GQ)
__global__ void k_gather(const float* __restrict__ wde, const float* __restrict__ mwde) {
    const int nb = (SLOTS + 255) / 256;
    const int grp = blockIdx.x / nb;
    const int e = (blockIdx.x - grp * nb) * 256 + threadIdx.x;
    if (e >= SLOTS) return;
    const int blk = e / LCAP;
    const int k = e - blk * LCAP;
    const bool valid = (k < g_scnt[blk]);
    const unsigned lin = valid ? g_linS[e] : 0u;
    const int l0 = grp * GQ;
    float wm[GQ], wn[GQ];
    #pragma unroll
    for (int i = 0; i < GQ; i++) wm[i] = __ldg(&mwde[(size_t)(l0 + i) * MNdim + lin]);
    #pragma unroll
    for (int i = 0; i < GQ; i++) {
        int ln = l0 + i + 1;
        wn[i] = (ln < Lnum) ? __ldg(&wde[(size_t)ln * MNdim + lin]) : 0.0f;
    }
    #pragma unroll
    for (int i = 0; i < GQ; i++) {
        float2 p; p.x = wm[i]; p.y = wn[i];
        g_wmn[(size_t)(l0 + i) * SLOTS + e] = p;
    }
}

// ---------------- main BP recurrence: COLUMN-partitioned, CLSZ=16 ----------------
// floats: msgs LCAP | d LCAP | wmn 2*LCAP | colC 128 | P 512 | pp 512 | sign2 512 |
//         err 128 | offf 32 | resw 32 | rho 32 | lacc 32
// u16: rowE LCAP | permR LCAP | colptr 132 | rowptrR 516 ; u8: jE LCAP
#define SMEM_BYTES ((4*LCAP + 128 + 512 + 512 + 512 + 128 + 128) * 4 \
                    + (2*LCAP + 132 + 516) * 2 + LCAP)

__global__ void __launch_bounds__(NTH, 1) __cluster_dims__(CLSZ, 1, 1)
k_main(const int*   __restrict__ synd,
       const int*   __restrict__ errs,
       const float* __restrict__ llrs,
       const float* __restrict__ wllr,
       const float* __restrict__ mwllr,
       const float* __restrict__ resw,
       float* __restrict__ out)
{
    extern __shared__ char sm_raw[];
    float*  s_msgs  = (float*)sm_raw;                // LCAP
    float*  s_d     = s_msgs + LCAP;                 // LCAP
    float2* s_wmn   = (float2*)(s_d + LCAP);         // LCAP float2
    float*  s_colC  = (float*)(s_wmn + LCAP);        // 128 (owned cols, combined input)
    float*  s_P     = s_colC + CPC;                  // 512 (combined row products)
    float*  s_pp    = s_P + Mdim;                    // 512 (local partial products)
    float*  s_sign2 = s_pp + Mdim;                   // 512
    float*  s_err   = s_sign2 + Mdim;                // 128
    float*  s_offf  = s_err + CPC;                   // 32
    float*  s_resw  = s_offf + ROWN;                 // 32
    float*  s_rho   = s_resw + 32;                   // 32
    float*  s_lacc  = s_rho + 32;                    // 32
    unsigned short* s_rowE   = (unsigned short*)(s_lacc + 32);   // LCAP
    unsigned short* s_permR  = s_rowE + LCAP;                     // LCAP
    unsigned short* s_colptr = s_permR + LCAP;                    // 129 (+3 pad)
    unsigned short* s_rowptr = s_colptr + 132;                    // 513 (+3 pad)
    unsigned char*  s_jE     = (unsigned char*)(s_rowptr + 516);  // LCAP

    cg::cluster_group cl = cg::this_cluster();
    const int rank = (int)cl.block_rank();
    const int b    = blockIdx.x / CLSZ;
    const int tid  = threadIdx.x;
    const int lane = tid & 31;
    const int wid  = tid >> 5;
    const float OME = 1.0f - EPSV;
    const unsigned u_wmn = (unsigned)__cvta_generic_to_shared(s_wmn);
    const int j0 = rank * CPC;

    const int cnt = min(g_scnt[rank], LCAP);
    const int n16 = (cnt + 1) >> 1;

    // ---- prologue ----
    for (int k = tid; k < cnt; k += NTH) {
        s_rowE[k]  = g_rowE[rank * LCAP + k];
        s_permR[k] = g_permR[rank * LCAP + k];
        s_jE[k]    = g_jE[rank * LCAP + k];
        s_msgs[k]  = 0.0f;
    }
    if (tid <= CPC)  s_colptr[tid] = (unsigned short)g_colptrS[rank * (CPC + 1) + tid];
    if (tid <= Mdim) {
        if (tid < 513) {} // noop to keep structure
    }
    for (int r = tid; r <= Mdim; r += NTH)
        s_rowptr[r] = (unsigned short)g_rowptrR[rank * (Mdim + 1) + r];
    if (tid < Mdim)
        s_sign2[tid] = 2.0f * (1.0f - 2.0f * (float)synd[b * Mdim + tid]);
    if (tid < ROWN) {
        int row = rank * ROWN + tid;
        int d = g_rowptr[row + 1] - g_rowptr[row];
        s_offf[tid] = powf(OME, (float)(Ndim - d));
    }
    if (tid < CPC) {
        s_err[tid]  = 1.0f - (float)errs[b * Ndim + j0 + tid];
        s_colC[tid] = llrs[j0 + tid] * wllr[j0 + tid];   // layer-0 input
    }
    if (tid < Lnum) { s_resw[tid] = resw[tid]; s_rho[tid] = g_rho[tid]; }
    __syncthreads();

    float acc = 0.0f;
    for (int l = 0; l < Lnum; l++) {
        const float rw = s_resw[l];
        const bool lastL = (l == Lnum - 1);

        // ---- stage this layer's weights (used only in the late column pass) ----
        {
            const float2* src = &g_wmn[(size_t)l * SLOTS + rank * LCAP];
            for (int q = tid; q < n16; q += NTH)
                cpasync16(u_wmn + (unsigned)q * 16u, src + q * 2);
            asm volatile("cp.async.commit_group;");
        }

        // ---- phase A: entry-parallel tanh ----
        for (int k = tid; k < cnt; k += NTH) {
            float men = s_colC[s_jE[k]] - s_msgs[k];
            float d;
            asm("tanh.approx.f32 %0, %1;" : "=f"(d) : "f"(0.5f * men));
            if (d == 0.0f) d = 1.0f;
            d = fminf(fmaxf(d, -OME), OME);
            s_d[k] = d;
        }
        __syncthreads();

        // ---- phase B: local partial row products (thread per row, ~2.6 entries) ----
        if (tid < Mdim) {
            int st = s_rowptr[tid], en = s_rowptr[tid + 1];
            float p = 1.0f;
            for (int t2 = st; t2 < en; t2++) p *= s_d[s_permR[t2]];
            s_pp[tid] = p;
        }
        CLUSTER_ARRIVE();
        CLUSTER_WAIT();

        // ---- phase C: combine owned rows' products across 16 CTAs + broadcast ----
        if (tid < ROWN) {
            const int row = rank * ROWN + tid;
            float P = s_offf[tid];
            #pragma unroll
            for (int r = 0; r < CLSZ; r++)
                P *= ((const float*)cl.map_shared_rank(s_pp, r))[row];
            #pragma unroll
            for (int r = 0; r < CLSZ; r++)
                ((float*)cl.map_shared_rank(s_P, r))[row] = P;
        }
        CLUSTER_ARRIVE();
        CLUSTER_WAIT();

        // ---- phase D: entry-parallel message update ----
        for (int k = tid; k < cnt; k += NTH) {
            float d = s_d[k];
            int row = s_rowE[k];
            float r = __fdividef(s_P[row], d);
            float ath = (fabsf(r) < 6.25e-3f) ? r * (1.0f + (1.0f / 3.0f) * r * r)
                                              : atanhf(r);
            s_msgs[k] = s_sign2[row] * ath + rw * s_msgs[k];
        }
        asm volatile("cp.async.wait_group 0;" ::: "memory");
        __syncthreads();

        // ---- phase E: local column pass (4 threads/col) + loss ----
        if (tid < 4 * CPC) {
            const int c = tid >> 2;
            const int sub = tid & 3;
            const int st = s_colptr[c], en = s_colptr[c + 1];
            float cs = 0.0f, bs = 0.0f;
            for (int t2 = st + sub; t2 < en; t2 += 4) {
                float m = s_msgs[t2];
                float2 w = s_wmn[t2];
                bs += m * w.x;
                cs += m * w.y;
            }
            // reduce within group of 4
            cs += __shfl_down_sync(0xffffffffu, cs, 1, 4);
            cs += __shfl_down_sync(0xffffffffu, cs, 2, 4);
            bs += __shfl_down_sync(0xffffffffu, bs, 1, 4);
            bs += __shfl_down_sync(0xffffffffu, bs, 2, 4);
            if (sub == 0) {
                const int jg = j0 + c;
                float lv = llrs[jg];
                if (!lastL) s_colC[c] = lv * wllr[(size_t)(l + 1) * Ndim + jg] + cs;
                float x = lv * mwllr[(size_t)l * Ndim + jg] + bs;
                float sp = fmaxf(x, 0.0f) + log1pf(__expf(-fabsf(x)));
                acc += s_rho[l] * (sp - s_err[c] * x);
            }
        }
        __syncthreads();
    }

    // ---- loss reduce ----
    for (int o = 16; o; o >>= 1) acc += __shfl_xor_sync(0xffffffffu, acc, o);
    if (lane == 0) s_lacc[wid] = acc;
    __syncthreads();
    if (tid == 0) {
        float s = 0.0f;
        #pragma unroll
        for (int w = 0; w < 32; w++) s += s_lacc[w];
        atomicAdd(out, s * (1.0f / (float)Bsz));
    }
}

// ---------------- host launcher ----------------
extern "C" void kernel_launch(void* const* d_in, const int* in_sizes, int n_in,
                              void* d_out, int out_size) {
    const int*   synd  = (const int*)d_in[0];
    const int*   errs  = (const int*)d_in[1];
    const float* H     = (const float*)d_in[2];
    const float* llrs  = (const float*)d_in[3];
    const float* wde   = (const float*)d_in[4];
    const float* wllr  = (const float*)d_in[5];
    const float* mwde  = (const float*)d_in[6];
    const float* mwllr = (const float*)d_in[7];
    const float* rhos  = (const float*)d_in[8];
    const float* resw  = (const float*)d_in[9];
    float* out = (float*)d_out;

    cudaFuncSetAttribute(k_main, cudaFuncAttributeMaxDynamicSharedMemorySize, SMEM_BYTES);
    cudaFuncSetAttribute(k_main, cudaFuncAttributeNonPortableClusterSizeAllowed, 1);

    k_prep1<<<Mdim, 512>>>((const float4*)H);
    k_prep2<<<1, Mdim>>>(rhos, out);
    k_prep3<<<CLSZ, 1024>>>();
    k_gather<<<GGROUPS * ((SLOTS + 255) / 256), 256>>>(wde, mwde);
    k_main<<<Bsz * CLSZ, NTH, SMEM_BYTES>>>(synd, errs, llrs, wllr, mwllr, resw, out);
}